// round 4
// baseline (speedup 1.0000x reference)
#include <cuda_runtime.h>
#include <cstdint>

#define F_DIM 256
#define NB 32
#define P_DIM 32

// Global scratch for the two sensitive-feature histograms (2 x 32 bins).
// Zeroed by a dedicated kernel each launch so graph replays are deterministic.
__device__ int g_hist[64];

__global__ void zero_hist_kernel() {
    int t = threadIdx.x;
    if (t < 64) g_hist[t] = 0;
}

// Bin index. UNI = bins verified to be exactly k/32 (fast path, no LDS).
// Fallback exactly reproduces the reference: count(x >= edge) - 1, clipped.
template <bool UNI>
__device__ __forceinline__ int bin_of(float v, const float* __restrict__ e) {
    if (UNI) {
        int k = (int)(v * 32.0f);
        k = k < 0 ? 0 : k;
        return k > 31 ? 31 : k;
    } else {
        int c = 0;
#pragma unroll
        for (int k = 0; k < 33; ++k) c += (v >= e[k]) ? 1 : 0;
        c -= 1;
        c = c < 0 ? 0 : c;
        return c > 31 ? 31 : c;
    }
}

template <bool UNI>
__device__ __forceinline__ void process_rows(
    const float* __restrict__ x, float* __restrict__ out,
    const float* __restrict__ sW, const float* __restrict__ sIW,
    const float* __restrict__ sBins,
    unsigned* __restrict__ myIdx, int* __restrict__ sHist,
    int lane, int pi, int pj, int gw, int nw, int B, float icpt)
{
    const unsigned char* ib = (const unsigned char*)myIdx;
    const int fa = 4 * lane;
    const int fc = 128 + 4 * lane;
    for (int row = gw; row < B; row += nw) {
        const float4* rp = (const float4*)(x + (size_t)row * F_DIM);
        // Two fully coalesced 512B warp loads cover the 1KB row.
        float4 a = rp[lane];
        float4 c = rp[32 + lane];

        int i0 = bin_of<UNI>(a.x, sBins + (fa + 0) * 33);
        int i1 = bin_of<UNI>(a.y, sBins + (fa + 1) * 33);
        int i2 = bin_of<UNI>(a.z, sBins + (fa + 2) * 33);
        int i3 = bin_of<UNI>(a.w, sBins + (fa + 3) * 33);
        int i4 = bin_of<UNI>(c.x, sBins + (fc + 0) * 33);
        int i5 = bin_of<UNI>(c.y, sBins + (fc + 1) * 33);
        int i6 = bin_of<UNI>(c.z, sBins + (fc + 2) * 33);
        int i7 = bin_of<UNI>(c.w, sBins + (fc + 3) * 33);

        // Main-effect gathers (W padded to stride 33 -> bank = (4l+j+idx)%32).
        float s = sW[(fa + 0) * 33 + i0] + sW[(fa + 1) * 33 + i1]
                + sW[(fa + 2) * 33 + i2] + sW[(fa + 3) * 33 + i3]
                + sW[(fc + 0) * 33 + i4] + sW[(fc + 1) * 33 + i5]
                + sW[(fc + 2) * 33 + i6] + sW[(fc + 3) * 33 + i7];

        // Publish packed bin indices: byte offset == feature index (0..255).
        myIdx[lane]      = (unsigned)i0 | ((unsigned)i1 << 8) | ((unsigned)i2 << 16) | ((unsigned)i3 << 24);
        myIdx[32 + lane] = (unsigned)i4 | ((unsigned)i5 << 8) | ((unsigned)i6 << 16) | ((unsigned)i7 << 24);

        // Sensitive-feature histograms: feature 0 = lane0/.x, feature 5 = lane1/.y
        if (lane == 0) atomicAdd(&sHist[i0], 1);
        if (lane == 1) atomicAdd(&sHist[32 + i1], 1);

        __syncwarp();

        // Interaction term: lane p handles pair p, fully generic in pair_i/pair_j.
        if (lane < P_DIM) {
            int ba = ib[pi];
            int bb = ib[pj];
            s += sIW[lane * (NB * NB) + ba * NB + bb];
        }

        // Warp tree-reduce; the shfl barrier also fences the WAR hazard on myIdx.
#pragma unroll
        for (int off = 16; off > 0; off >>= 1)
            s += __shfl_xor_sync(0xffffffffu, s, off);

        if (lane == 0) out[row] = icpt + s;
    }
}

__global__ __launch_bounds__(1024, 1)
void fair_ebm_kernel(const float* __restrict__ x, const float* __restrict__ W,
                     const float* __restrict__ IW, const float* __restrict__ intercept,
                     const float* __restrict__ bins, const int* __restrict__ pair_i,
                     const int* __restrict__ pair_j, float* __restrict__ out, int B)
{
    extern __shared__ float smem[];
    float*    sW    = smem;                                   // 256*33 floats (pad 33)
    float*    sIW   = sW + F_DIM * 33;                        // 32*1024 floats
    float*    sBins = sIW + P_DIM * NB * NB;                  // 256*33 floats
    unsigned* sIdx  = (unsigned*)(sBins + F_DIM * 33);        // 32 warps * 64 words
    int*      sHist = (int*)(sIdx + 32 * 64);                 // 64 ints
    int*      sFlag = sHist + 64;                             // 1 int

    const int tid = threadIdx.x;
    if (tid == 0) sFlag[0] = 1;
    if (tid < 64) sHist[tid] = 0;

    // Stage W with bank padding.
    for (int i = tid; i < F_DIM * NB; i += 1024)
        sW[(i >> 5) * 33 + (i & 31)] = W[i];
    // Stage IW contiguously.
    for (int i = tid; i < P_DIM * NB * NB; i += 1024)
        sIW[i] = IW[i];
    // Stage bins and verify they are exactly the uniform k/32 grid.
    {
        bool bad = false;
        for (int i = tid; i < F_DIM * 33; i += 1024) {
            float v = bins[i];
            sBins[i] = v;
            int k = i % 33;
            if (v != (float)k * 0.03125f) bad = true;
        }
        if (bad) sFlag[0] = 0;   // benign race: any writer writes 0
    }
    __syncthreads();

    const bool  uni  = (sFlag[0] != 0);
    const float icpt = intercept[0];
    const int lane = tid & 31;
    const int warp = tid >> 5;
    const int pi = pair_i[lane & (P_DIM - 1)];
    const int pj = pair_j[lane & (P_DIM - 1)];
    unsigned* myIdx = sIdx + warp * 64;

    const int gw = blockIdx.x * (blockDim.x >> 5) + warp;
    const int nw = gridDim.x * (blockDim.x >> 5);

    if (uni)
        process_rows<true >(x, out, sW, sIW, sBins, myIdx, sHist, lane, pi, pj, gw, nw, B, icpt);
    else
        process_rows<false>(x, out, sW, sIW, sBins, myIdx, sHist, lane, pi, pj, gw, nw, B, icpt);

    __syncthreads();
    if (tid < 64) atomicAdd(&g_hist[tid], sHist[tid]);
}

// Exact fairness loss from integer histograms, double precision.
__global__ void finalize_kernel(const float* __restrict__ W, float* __restrict__ out, int B)
{
    if (threadIdx.x == 0 && blockIdx.x == 0) {
        const int sens[2] = {0, 5};
        double loss = 0.0;
        for (int s = 0; s < 2; ++s) {
            const float* w = W + sens[s] * NB;
            double s1 = 0.0, s2 = 0.0;
            for (int k = 0; k < NB; ++k) {
                double cnt = (double)g_hist[s * 32 + k];
                double wv  = (double)w[k];
                s1 += cnt * wv;
                s2 += cnt * wv * wv;
            }
            double mean = s1 / (double)B;
            loss += s2 / (double)B - mean * mean;
        }
        out[B] = (float)(0.1 * loss);
    }
}

extern "C" void kernel_launch(void* const* d_in, const int* in_sizes, int n_in,
                              void* d_out, int out_size)
{
    const float* x         = (const float*)d_in[0];
    const float* W         = (const float*)d_in[1];
    const float* IW        = (const float*)d_in[2];
    const float* intercept = (const float*)d_in[3];
    const float* bins      = (const float*)d_in[4];
    const int*   pair_i    = (const int*)d_in[5];
    const int*   pair_j    = (const int*)d_in[6];
    float*       out       = (float*)d_out;

    // Output = [preds (B floats), fairness_loss (1 float)]
    int B = out_size - 1;
    if ((long long)B * F_DIM != (long long)in_sizes[0]) B = in_sizes[0] / F_DIM;

    int dev = 0;
    cudaGetDevice(&dev);
    int sms = 148;
    cudaDeviceGetAttribute(&sms, cudaDevAttrMultiProcessorCount, dev);

    const size_t shbytes =
        (size_t)(F_DIM * 33 + P_DIM * NB * NB + F_DIM * 33 + 32 * 64) * 4 + 64 * 4 + 16;
    cudaFuncSetAttribute(fair_ebm_kernel,
                         cudaFuncAttributeMaxDynamicSharedMemorySize, (int)shbytes);

    zero_hist_kernel<<<1, 64>>>();
    fair_ebm_kernel<<<sms, 1024, shbytes>>>(x, W, IW, intercept, bins,
                                            pair_i, pair_j, out, B);
    if (out_size > B)
        finalize_kernel<<<1, 32>>>(W, out, B);
}

// round 5
// speedup vs baseline: 1.5019x; 1.5019x over previous
#include <cuda_runtime.h>

#define F_DIM 256
#define NB 32
#define P_DIM 32

// Cross-block accumulators. g_hist zero at process start (static init); the
// LAST block of every launch resets both to zero after consuming them, so
// each graph replay is deterministic. No extra kernels, no allocation.
__device__ int g_hist[64];
__device__ unsigned int g_ctr = 0;

// Bin index. UNI = bins verified on-device to be exactly k/32 (x*32 is an
// exact power-of-two scale in fp32, so floor(x*32) == count(x >= k/32)-1).
// Fallback exactly reproduces the reference binary-count semantics.
template <bool UNI>
__device__ __forceinline__ int bin_of(float v, const float* __restrict__ e) {
    if (UNI) {
        int k = (int)(v * 32.0f);
        k = k < 0 ? 0 : k;
        return k > 31 ? 31 : k;
    } else {
        int c = 0;
#pragma unroll
        for (int k = 0; k < 33; ++k) c += (v >= e[k]) ? 1 : 0;
        c -= 1;
        c = c < 0 ? 0 : c;
        return c > 31 ? 31 : c;
    }
}

template <bool UNI, bool PFAST>
__device__ __forceinline__ void process_rows(
    const float* __restrict__ x, float* __restrict__ out,
    const float* __restrict__ sW, const float* __restrict__ sIW,
    const float* __restrict__ sBins,
    unsigned* __restrict__ myIdx, int* __restrict__ sHist,
    int lane, int pi, int pj, int gw, int nw, int B, float icpt)
{
    const unsigned char* ib = (const unsigned char*)myIdx;
    const int fa = 4 * lane;
    const int fc = 128 + 4 * lane;

    int row = gw;
    if (row >= B) return;
    const float4* rp = (const float4*)(x + (size_t)row * F_DIM);
    float4 a = rp[lane];
    float4 c = rp[32 + lane];

    while (true) {
        // ---- prefetch next row (overlaps DRAM latency with compute) ----
        const int nrow = row + nw;
        const bool more = nrow < B;
        float4 a2, c2;
        if (more) {
            const float4* rp2 = (const float4*)(x + (size_t)nrow * F_DIM);
            a2 = rp2[lane];
            c2 = rp2[32 + lane];
        }

        // ---- bins ----
        int i0 = bin_of<UNI>(a.x, sBins + (fa + 0) * 33);
        int i1 = bin_of<UNI>(a.y, sBins + (fa + 1) * 33);
        int i2 = bin_of<UNI>(a.z, sBins + (fa + 2) * 33);
        int i3 = bin_of<UNI>(a.w, sBins + (fa + 3) * 33);
        int i4 = bin_of<UNI>(c.x, sBins + (fc + 0) * 33);
        int i5 = bin_of<UNI>(c.y, sBins + (fc + 1) * 33);
        int i6 = bin_of<UNI>(c.z, sBins + (fc + 2) * 33);
        int i7 = bin_of<UNI>(c.w, sBins + (fc + 3) * 33);

        // ---- main-effect gathers (W padded stride 33) ----
        float s = sW[(fa + 0) * 33 + i0] + sW[(fa + 1) * 33 + i1]
                + sW[(fa + 2) * 33 + i2] + sW[(fa + 3) * 33 + i3]
                + sW[(fc + 0) * 33 + i4] + sW[(fc + 1) * 33 + i5]
                + sW[(fc + 2) * 33 + i6] + sW[(fc + 3) * 33 + i7];

        const unsigned w0 = (unsigned)i0 | ((unsigned)i1 << 8)
                          | ((unsigned)i2 << 16) | ((unsigned)i3 << 24);

        // ---- interaction term ----
        if (PFAST) {
            // pairs are (2p, 2p+1): pair p's two bins live in byte-pair
            // (2*(p&1), 2*(p&1)+1) of lane p/2's packed word. One shfl.
            unsigned v = __shfl_sync(0xffffffffu, w0, lane >> 1);
            int sh = (lane & 1) << 4;
            int ba = (v >> sh) & 0xff;
            int bb = (v >> (sh + 8)) & 0xff;
            s += sIW[lane * (NB * NB) + ba * NB + bb];
        } else {
            const unsigned w1 = (unsigned)i4 | ((unsigned)i5 << 8)
                              | ((unsigned)i6 << 16) | ((unsigned)i7 << 24);
            myIdx[lane]      = w0;
            myIdx[32 + lane] = w1;
            __syncwarp();
            if (lane < P_DIM) {
                int ba = ib[pi];
                int bb = ib[pj];
                s += sIW[lane * (NB * NB) + ba * NB + bb];
            }
        }

        // ---- sensitive-feature histograms (features 0 and 5) ----
        if (lane == 0)      atomicAdd(&sHist[i0], 1);
        else if (lane == 1) atomicAdd(&sHist[32 + i1], 1);

        // ---- warp reduce; shfl sync also fences the myIdx WAR hazard ----
#pragma unroll
        for (int off = 16; off > 0; off >>= 1)
            s += __shfl_xor_sync(0xffffffffu, s, off);
        if (lane == 0) out[row] = icpt + s;

        if (!more) break;
        row = nrow; a = a2; c = c2;
    }
}

__global__ __launch_bounds__(1024, 1)
void fair_ebm_kernel(const float* __restrict__ x, const float* __restrict__ W,
                     const float* __restrict__ IW, const float* __restrict__ intercept,
                     const float* __restrict__ bins, const int* __restrict__ pair_i,
                     const int* __restrict__ pair_j, float* __restrict__ out,
                     int B, int writeLoss)
{
    extern __shared__ float smem[];
    float*    sW    = smem;                                  // 256*33
    float*    sIW   = sW + F_DIM * 33;                       // 32*1024
    float*    sBins = sIW + P_DIM * NB * NB;                 // 256*33
    unsigned* sIdx  = (unsigned*)(sBins + F_DIM * 33);       // 32 warps * 64
    int*      sHist = (int*)(sIdx + 32 * 64);                // 64
    int*      sFlag = sHist + 64;                            // 2

    const int tid = threadIdx.x;
    if (tid == 0) { sFlag[0] = 1; sFlag[1] = 1; }
    if (tid < 64) sHist[tid] = 0;
    __syncthreads();

    // ---- vectorized staging ----
    {   // W: 2048 float4 loads, padded scalar stores
        const float4* W4 = (const float4*)W;
        for (int i = tid; i < (F_DIM * NB) / 4; i += 1024) {
            float4 v = W4[i];
            int e = i * 4;
            float* d = sW + (e >> 5) * 33 + (e & 31);   // e&31 <= 28
            d[0] = v.x; d[1] = v.y; d[2] = v.z; d[3] = v.w;
        }
    }
    {   // IW: contiguous float4 copy
        const float4* IW4 = (const float4*)IW;
        float4* sIW4 = (float4*)sIW;
        for (int i = tid; i < (P_DIM * NB * NB) / 4; i += 1024) sIW4[i] = IW4[i];
    }
    {   // bins: stage + verify uniform grid k/32
        const float4* B4 = (const float4*)bins;
        bool bad = false;
        for (int i = tid; i < (F_DIM * 33) / 4; i += 1024) {
            float4 v = B4[i];
            int e = i * 4;
            sBins[e + 0] = v.x; sBins[e + 1] = v.y;
            sBins[e + 2] = v.z; sBins[e + 3] = v.w;
            bad |= (v.x != (float)((e + 0) % 33) * 0.03125f);
            bad |= (v.y != (float)((e + 1) % 33) * 0.03125f);
            bad |= (v.z != (float)((e + 2) % 33) * 0.03125f);
            bad |= (v.w != (float)((e + 3) % 33) * 0.03125f);
        }
        if (bad) sFlag[0] = 0;
    }
    int pi = 0, pj = 1;
    if (tid < P_DIM) {
        pi = pair_i[tid]; pj = pair_j[tid];
        if (pi != 2 * tid || pj != 2 * tid + 1) sFlag[1] = 0;
    }
    __syncthreads();

    const bool  uni   = (sFlag[0] != 0);
    const bool  pfast = (sFlag[1] != 0);
    const float icpt  = intercept[0];
    const int   lane  = tid & 31;
    const int   warp  = tid >> 5;
    unsigned*   myIdx = sIdx + warp * 64;
    const int   gw    = blockIdx.x * (blockDim.x >> 5) + warp;
    const int   nw    = gridDim.x * (blockDim.x >> 5);
    // lane-indexed pair values for the generic path
    int lpi = __shfl_sync(0xffffffffu, tid < P_DIM ? pi : 0, 0);
    (void)lpi;
    int gpi = (lane < P_DIM && warp == 0) ? pi : 0;
    (void)gpi;
    // re-load per-lane pair indices (L2-hot, generic path only)
    int mpi = pair_i[lane & (P_DIM - 1)];
    int mpj = pair_j[lane & (P_DIM - 1)];

    if (uni) {
        if (pfast) process_rows<true,  true >(x, out, sW, sIW, sBins, myIdx, sHist, lane, mpi, mpj, gw, nw, B, icpt);
        else       process_rows<true,  false>(x, out, sW, sIW, sBins, myIdx, sHist, lane, mpi, mpj, gw, nw, B, icpt);
    } else {
        if (pfast) process_rows<false, true >(x, out, sW, sIW, sBins, myIdx, sHist, lane, mpi, mpj, gw, nw, B, icpt);
        else       process_rows<false, false>(x, out, sW, sIW, sBins, myIdx, sHist, lane, mpi, mpj, gw, nw, B, icpt);
    }

    // ---- cross-block reduction + last-block finalize (single kernel) ----
    __syncthreads();
    if (tid < 64) atomicAdd(&g_hist[tid], sHist[tid]);
    __threadfence();
    __syncthreads();

    __shared__ unsigned ticket;
    if (tid == 0) ticket = atomicAdd(&g_ctr, 1u);
    __syncthreads();

    if (ticket == gridDim.x - 1) {
        // read the global totals atomically (bypasses any stale caching)
        if (tid < 64) sHist[tid] = atomicAdd(&g_hist[tid], 0);
        __syncthreads();

        if (tid < 32) {
            const double invB = 1.0 / (double)B;
            double vsum = 0.0;
#pragma unroll
            for (int sIdx2 = 0; sIdx2 < 2; ++sIdx2) {
                const int f = sIdx2 ? 5 : 0;
                double w   = (double)W[f * NB + tid];
                double cnt = (double)sHist[sIdx2 * 32 + tid];
                double t1 = cnt * w;
                double t2 = t1 * w;
#pragma unroll
                for (int off = 16; off > 0; off >>= 1) {
                    t1 += __shfl_xor_sync(0xffffffffu, t1, off);
                    t2 += __shfl_xor_sync(0xffffffffu, t2, off);
                }
                double mean = t1 * invB;
                vsum += t2 * invB - mean * mean;
            }
            if (tid == 0) {
                if (writeLoss) out[B] = (float)(0.1 * vsum);
                g_ctr = 0;                      // reset ticket for next replay
            }
        }
        if (tid < 64) g_hist[tid] = 0;          // reset hist for next replay
        __threadfence();
    }
}

extern "C" void kernel_launch(void* const* d_in, const int* in_sizes, int n_in,
                              void* d_out, int out_size)
{
    const float* x         = (const float*)d_in[0];
    const float* W         = (const float*)d_in[1];
    const float* IW        = (const float*)d_in[2];
    const float* intercept = (const float*)d_in[3];
    const float* bins      = (const float*)d_in[4];
    const int*   pair_i    = (const int*)d_in[5];
    const int*   pair_j    = (const int*)d_in[6];
    float*       out       = (float*)d_out;

    const int B = in_sizes[0] / F_DIM;          // output = [preds(B), loss(1)]
    const int writeLoss = (out_size > B) ? 1 : 0;

    int dev = 0;
    cudaGetDevice(&dev);
    int sms = 148;
    cudaDeviceGetAttribute(&sms, cudaDevAttrMultiProcessorCount, dev);

    const size_t shbytes =
        (size_t)(F_DIM * 33 + P_DIM * NB * NB + F_DIM * 33 + 32 * 64) * 4
        + 64 * 4 + 16;
    cudaFuncSetAttribute(fair_ebm_kernel,
                         cudaFuncAttributeMaxDynamicSharedMemorySize, (int)shbytes);

    fair_ebm_kernel<<<sms, 1024, shbytes>>>(x, W, IW, intercept, bins,
                                            pair_i, pair_j, out, B, writeLoss);
}